// round 6
// baseline (speedup 1.0000x reference)
#include <cuda_runtime.h>
#include <cuda_bf16.h>

// Problem constants
#define NN 1024
#define HH 16
#define DD 64
#define MM 64
#define NB (NN * HH)          // 16384 independent (n,h) pairs

static constexpr float MU_C  = 0.9f;
static constexpr float EPS_C = 1e-6f;

// R2 structure (best so far: DRAM 85%), single change: stores use DEFAULT
// cache policy (evict-normal) instead of .cs, so the 126MB L2 batches dirty
// writebacks into large bursts instead of eagerly evicting them interleaved
// with the read stream. Loads stay .cs (truly streaming, must not displace
// dirty lines).
__global__ __launch_bounds__(256, 5)
void rma_kernel(const float* __restrict__ q_in,
                const float* __restrict__ k_in,
                const float* __restrict__ v_in,
                const float* __restrict__ Si_in,
                const float* __restrict__ Zi_in,
                const float* __restrict__ Pi_in,
                float* __restrict__ Vout,
                float* __restrict__ Sout,
                float* __restrict__ Zout,
                float* __restrict__ Pout)
{
    const int b = blockIdx.x;          // n*H + h
    const int t = threadIdx.x;         // 0..255

    __shared__ float  sQ[DD];
    __shared__ float  sK[DD];
    __shared__ float  sVal[MM];
    __shared__ float  sDotPart[2];
    __shared__ float  sZ;
    __shared__ float4 sAcc[256];       // per-thread partial V accumulators

    const int base64   = b * 64;
    const int base4096 = b * 4096;

    const int g    = t & 15;           // float4 column group (m = 4g..4g+3)
    const int drow = t >> 4;           // 0..15

    const float4* __restrict__ Pi4 = (const float4*)(Pi_in + base4096);
    const float4* __restrict__ Si4 = (const float4*)(Si_in + base4096);

    // ---- hoisted big-matrix loads: front-batched, evict-first ----
    const int o0 = (drow +  0) * 16 + g;
    const int o1 = (drow + 16) * 16 + g;
    const int o2 = (drow + 32) * 16 + g;
    const int o3 = (drow + 48) * 16 + g;
    float4 p0 = __ldcs(Pi4 + o0);
    float4 p1 = __ldcs(Pi4 + o1);
    float4 p2 = __ldcs(Pi4 + o2);
    float4 p3 = __ldcs(Pi4 + o3);
    float4 s0 = __ldcs(Si4 + o0);
    float4 s1 = __ldcs(Si4 + o1);
    float4 s2 = __ldcs(Si4 + o2);
    float4 s3 = __ldcs(Si4 + o3);

    // ---- small vectors: featurize, Zi update, partial dot (overlaps big loads) ----
    if (t < DD) {
        float xq = q_in[base64 + t];
        float fq = (xq > 0.f) ? (xq + 1.f) : __expf(xq);   // elu(x)+1
        sQ[t] = fq;

        float xk = k_in[base64 + t];
        float fk = (xk > 0.f) ? (xk + 1.f) : __expf(xk);
        sK[t] = fk;

        float zn = Zi_in[base64 + t] + fk;
        Zout[base64 + t] = zn;

        float d = fq * zn;
        #pragma unroll
        for (int off = 16; off > 0; off >>= 1)
            d += __shfl_down_sync(0xffffffffu, d, off);
        if ((t & 31) == 0) sDotPart[t >> 5] = d;
    } else if (t < 128) {
        sVal[t - 64] = v_in[base64 + (t - 64)];
    }
    __syncthreads();

    if (t == 0) sZ = 1.0f / (sDotPart[0] + sDotPart[1] + EPS_C);
    // (sZ only read after the second __syncthreads)

    const float4 val4 = ((const float4*)sVal)[g];
    const float kk0 = sK[drow +  0], qq0 = sQ[drow +  0];
    const float kk1 = sK[drow + 16], qq1 = sQ[drow + 16];
    const float kk2 = sK[drow + 32], qq2 = sQ[drow + 32];
    const float kk3 = sK[drow + 48], qq3 = sQ[drow + 48];

    float4* __restrict__ So4 = (float4*)(Sout + base4096);
    float4* __restrict__ Po4 = (float4*)(Pout + base4096);

    float4 vacc = make_float4(0.f, 0.f, 0.f, 0.f);

    #define DO_ROW(pp, ss, kk, qq, oo)                              \
    {                                                               \
        float4 pn, sn;                                              \
        pn.x = MU_C * (pp).x - (kk) * val4.x;                       \
        pn.y = MU_C * (pp).y - (kk) * val4.y;                       \
        pn.z = MU_C * (pp).z - (kk) * val4.z;                       \
        pn.w = MU_C * (pp).w - (kk) * val4.w;                       \
        sn.x = (ss).x - pn.x;                                       \
        sn.y = (ss).y - pn.y;                                       \
        sn.z = (ss).z - pn.z;                                       \
        sn.w = (ss).w - pn.w;                                       \
        Po4[oo] = pn;                                               \
        So4[oo] = sn;                                               \
        vacc.x += (qq) * sn.x;                                      \
        vacc.y += (qq) * sn.y;                                      \
        vacc.z += (qq) * sn.z;                                      \
        vacc.w += (qq) * sn.w;                                      \
    }

    DO_ROW(p0, s0, kk0, qq0, o0)
    DO_ROW(p1, s1, kk1, qq1, o1)
    DO_ROW(p2, s2, kk2, qq2, o2)
    DO_ROW(p3, s3, kk3, qq3, o3)

    #undef DO_ROW

    sAcc[t] = vacc;
    __syncthreads();

    // ---- V readout: reduce 16 row-partials per m, scale by Z ----
    if (t < MM) {
        const int gg = t >> 2;
        const int c  = t & 3;
        const float* accf = (const float*)sAcc;
        float sum = 0.f;
        #pragma unroll
        for (int r = 0; r < 16; ++r)
            sum += accf[(r * 16 + gg) * 4 + c];
        Vout[base64 + t] = sum * sZ;
    }
}

extern "C" void kernel_launch(void* const* d_in, const int* in_sizes, int n_in,
                              void* d_out, int out_size) {
    // metadata order: query, key, value, Si, Zi, Pi
    const float* q  = (const float*)d_in[0];
    const float* k  = (const float*)d_in[1];
    const float* v  = (const float*)d_in[2];
    const float* Si = (const float*)d_in[3];
    const float* Zi = (const float*)d_in[4];
    const float* Pi = (const float*)d_in[5];

    float* out = (float*)d_out;
    // reference returns (V, Si_new, Zi_new, Pi_new) -> concatenated flat
    float* Vout = out;
    float* Sout = Vout + (size_t)NN * HH * MM;
    float* Zout = Sout + (size_t)NN * HH * DD * MM;
    float* Pout = Zout + (size_t)NN * HH * DD;

    rma_kernel<<<NB, 256>>>(q, k, v, Si, Zi, Pi, Vout, Sout, Zout, Pout);
}

// round 7
// speedup vs baseline: 1.0318x; 1.0318x over previous
#include <cuda_runtime.h>
#include <cuda_bf16.h>

#define NN 1024
#define HH 16
#define DD 64
#define MM 64
#define NB (NN * HH)          // 16384 independent (n,h) pairs

static constexpr float MU_C  = 0.9f;
static constexpr float EPS_C = 1e-6f;

// One CTA per (n,h), 128 threads, 16 front-batched float4 loads per thread
// (MLP_p1 = 16). Thread t: column group g = t & 15 (m = 4g..4g+3), row-octet
// drow8 = t >> 4 (0..7); rows d = drow8 + 8*it, it = 0..7. Warp covers two
// adjacent rows per it -> 512B contiguous per load/store. Stores are a long
// back-to-back .cs burst (32 per warp). kk/qq come from smem per-row (LDS,
// cheap) so the 64 data registers dominate and we fit the 102-reg cap.
__global__ __launch_bounds__(128, 5)
void rma_kernel(const float* __restrict__ q_in,
                const float* __restrict__ k_in,
                const float* __restrict__ v_in,
                const float* __restrict__ Si_in,
                const float* __restrict__ Zi_in,
                const float* __restrict__ Pi_in,
                float* __restrict__ Vout,
                float* __restrict__ Sout,
                float* __restrict__ Zout,
                float* __restrict__ Pout)
{
    const int b = blockIdx.x;
    const int t = threadIdx.x;         // 0..127

    __shared__ float  sQ[DD];
    __shared__ float  sK[DD];
    __shared__ float  sVal[MM];
    __shared__ float  sDotPart[2];
    __shared__ float  sZ;
    __shared__ float4 sAcc[128];

    const int base64   = b * 64;
    const int base4096 = b * 4096;

    const int g     = t & 15;          // float4 column group
    const int drow8 = t >> 4;          // 0..7

    const float4* __restrict__ Pi4 = (const float4*)(Pi_in + base4096);
    const float4* __restrict__ Si4 = (const float4*)(Si_in + base4096);

    // base float4 index; row it adds 8*16 = 128 float4 (2048B immediate)
    const int ob = drow8 * 16 + g;

    // ---- 16 front-batched loads (evict-first) ----
    float4 p0 = __ldcs(Pi4 + ob + 0 * 128);
    float4 p1 = __ldcs(Pi4 + ob + 1 * 128);
    float4 p2 = __ldcs(Pi4 + ob + 2 * 128);
    float4 p3 = __ldcs(Pi4 + ob + 3 * 128);
    float4 p4 = __ldcs(Pi4 + ob + 4 * 128);
    float4 p5 = __ldcs(Pi4 + ob + 5 * 128);
    float4 p6 = __ldcs(Pi4 + ob + 6 * 128);
    float4 p7 = __ldcs(Pi4 + ob + 7 * 128);
    float4 s0 = __ldcs(Si4 + ob + 0 * 128);
    float4 s1 = __ldcs(Si4 + ob + 1 * 128);
    float4 s2 = __ldcs(Si4 + ob + 2 * 128);
    float4 s3 = __ldcs(Si4 + ob + 3 * 128);
    float4 s4 = __ldcs(Si4 + ob + 4 * 128);
    float4 s5 = __ldcs(Si4 + ob + 5 * 128);
    float4 s6 = __ldcs(Si4 + ob + 6 * 128);
    float4 s7 = __ldcs(Si4 + ob + 7 * 128);

    // ---- small vectors: featurize, Zi update, partial dot (overlaps loads) ----
    if (t < DD) {
        float xq = q_in[base64 + t];
        float fq = (xq > 0.f) ? (xq + 1.f) : __expf(xq);   // elu(x)+1
        sQ[t] = fq;

        float xk = k_in[base64 + t];
        float fk = (xk > 0.f) ? (xk + 1.f) : __expf(xk);
        sK[t] = fk;

        float zn = Zi_in[base64 + t] + fk;
        Zout[base64 + t] = zn;

        float d = fq * zn;
        #pragma unroll
        for (int off = 16; off > 0; off >>= 1)
            d += __shfl_down_sync(0xffffffffu, d, off);
        if ((t & 31) == 0) sDotPart[t >> 5] = d;
    } else {
        sVal[t - 64] = v_in[base64 + (t - 64)];
    }
    __syncthreads();

    if (t == 0) sZ = 1.0f / (sDotPart[0] + sDotPart[1] + EPS_C);
    // (sZ only read after the second __syncthreads)

    const float4 val4 = ((const float4*)sVal)[g];

    float4* __restrict__ Po4 = (float4*)(Pout + base4096);
    float4* __restrict__ So4 = (float4*)(Sout + base4096);

    float4 vacc = make_float4(0.f, 0.f, 0.f, 0.f);

    #define DO_ROW(pp, ss, it)                                      \
    {                                                               \
        const float kk = sK[drow8 + 8 * (it)];                      \
        const float qq = sQ[drow8 + 8 * (it)];                      \
        float4 pn, sn;                                              \
        pn.x = MU_C * (pp).x - kk * val4.x;                         \
        pn.y = MU_C * (pp).y - kk * val4.y;                         \
        pn.z = MU_C * (pp).z - kk * val4.z;                         \
        pn.w = MU_C * (pp).w - kk * val4.w;                         \
        sn.x = (ss).x - pn.x;                                       \
        sn.y = (ss).y - pn.y;                                       \
        sn.z = (ss).z - pn.z;                                       \
        sn.w = (ss).w - pn.w;                                       \
        __stcs(Po4 + ob + (it) * 128, pn);                          \
        __stcs(So4 + ob + (it) * 128, sn);                          \
        vacc.x += qq * sn.x;                                        \
        vacc.y += qq * sn.y;                                        \
        vacc.z += qq * sn.z;                                        \
        vacc.w += qq * sn.w;                                        \
    }

    DO_ROW(p0, s0, 0)
    DO_ROW(p1, s1, 1)
    DO_ROW(p2, s2, 2)
    DO_ROW(p3, s3, 3)
    DO_ROW(p4, s4, 4)
    DO_ROW(p5, s5, 5)
    DO_ROW(p6, s6, 6)
    DO_ROW(p7, s7, 7)
    #undef DO_ROW

    sAcc[t] = vacc;
    __syncthreads();

    // ---- V readout: reduce 8 row-octet partials per m, scale by Z ----
    if (t < MM) {
        const int gg = t >> 2;
        const int c  = t & 3;
        const float* accf = (const float*)sAcc;
        float sum = 0.f;
        #pragma unroll
        for (int r = 0; r < 8; ++r)
            sum += accf[(r * 16 + gg) * 4 + c];
        Vout[base64 + t] = sum * sZ;
    }
}

extern "C" void kernel_launch(void* const* d_in, const int* in_sizes, int n_in,
                              void* d_out, int out_size) {
    // metadata order: query, key, value, Si, Zi, Pi
    const float* q  = (const float*)d_in[0];
    const float* k  = (const float*)d_in[1];
    const float* v  = (const float*)d_in[2];
    const float* Si = (const float*)d_in[3];
    const float* Zi = (const float*)d_in[4];
    const float* Pi = (const float*)d_in[5];

    float* out = (float*)d_out;
    // reference returns (V, Si_new, Zi_new, Pi_new) -> concatenated flat
    float* Vout = out;
    float* Sout = Vout + (size_t)NN * HH * MM;
    float* Zout = Sout + (size_t)NN * HH * DD * MM;
    float* Pout = Zout + (size_t)NN * HH * DD;

    rma_kernel<<<NB, 128>>>(q, k, v, Si, Zi, Pi, Vout, Sout, Zout, Pout);
}